// round 2
// baseline (speedup 1.0000x reference)
#include <cuda_runtime.h>
#include <cstdint>
#include <cstddef>

// Problem dims
#define TT 1024
#define BB 64
#define HH 256
#define G3 768   // 3*H
#define NC 64    // CTAs per direction in recurrent kernel
#define HC 4     // hidden units per CTA (NC*HC = HH)

// ---------------------------------------------------------------------------
// Static device scratch (no allocations allowed).
// g_gx layout: [dir][t][gate_row 0..767][b 0..63]  (b contiguous for coalesced
// per-step reads in the recurrent kernel).
// ---------------------------------------------------------------------------
__device__ float    g_gx[2][TT][G3][BB];      // ~402 MB
__device__ float    g_hbuf[2][2][HH * BB];    // double-buffered h, [k][b] layout
__device__ unsigned g_count[2];
__device__ unsigned g_phase[2];

// Sense-reversing grid barrier per direction. State self-resets each barrier
// (count back to 0, phase monotonically increasing) so it is safe across
// graph replays. Release/acquire chain makes all pre-barrier global writes
// visible after the barrier.
__device__ __forceinline__ void dir_barrier(int dir) {
    __syncthreads();
    if (threadIdx.x == 0) {
        unsigned* cnt = &g_count[dir];
        unsigned* phs = &g_phase[dir];
        unsigned ph;
        asm volatile("ld.acquire.gpu.global.u32 %0, [%1];"
                     : "=r"(ph) : "l"(phs) : "memory");
        unsigned prev;
        asm volatile("atom.acq_rel.gpu.global.add.u32 %0, [%1], %2;"
                     : "=r"(prev) : "l"(cnt), "r"(1u) : "memory");
        if (prev == NC - 1) {
            asm volatile("st.relaxed.gpu.global.u32 [%0], %1;"
                         :: "l"(cnt), "r"(0u) : "memory");
            asm volatile("red.release.gpu.global.add.u32 [%0], %1;"
                         :: "l"(phs), "r"(1u) : "memory");
        } else {
            unsigned cur;
            do {
                asm volatile("ld.acquire.gpu.global.u32 %0, [%1];"
                             : "=r"(cur) : "l"(phs) : "memory");
            } while (cur == ph);
        }
    }
    __syncthreads();
}

// ---------------------------------------------------------------------------
// Kernel 1: gx[d][t][g][b] = bias_d[g] + sum_i X[b][t][i] * wih_d[g][i]
// Tiled SGEMM: 64 (g) x 64 (b) tile per CTA, K=256 in chunks of 32.
// grid = (T, 768/64, 2), block = 256.
// ---------------------------------------------------------------------------
__global__ void __launch_bounds__(256) gx_gemm(
    const float* __restrict__ X,
    const float* __restrict__ wih_f, const float* __restrict__ bih_f,
    const float* __restrict__ bhh_f,
    const float* __restrict__ wih_b, const float* __restrict__ bih_b,
    const float* __restrict__ bhh_b)
{
    __shared__ float Xs[32][68];   // [k][b]
    __shared__ float Ws[32][68];   // [k][g_local]

    const int t  = blockIdx.x;
    const int g0 = blockIdx.y * 64;
    const int d  = blockIdx.z;
    const float* w  = d ? wih_b : wih_f;
    const float* b1 = d ? bih_b : bih_f;
    const float* b2 = d ? bhh_b : bhh_f;

    const int tid = threadIdx.x;
    const int tx  = tid & 15;   // b quad
    const int ty  = tid >> 4;   // g quad

    float acc[4][4] = {};

    for (int k0 = 0; k0 < 256; k0 += 32) {
        __syncthreads();
#pragma unroll
        for (int i = 0; i < 2; i++) {
            int idx = tid + i * 256;   // 0..511
            int row = idx >> 3;        // 0..63
            int kq  = idx & 7;         // 0..7
            float4 xv = *(const float4*)(X + ((size_t)row * TT + t) * 256 + k0 + kq * 4);
            Xs[kq * 4 + 0][row] = xv.x;
            Xs[kq * 4 + 1][row] = xv.y;
            Xs[kq * 4 + 2][row] = xv.z;
            Xs[kq * 4 + 3][row] = xv.w;
            float4 wv = *(const float4*)(w + (size_t)(g0 + row) * 256 + k0 + kq * 4);
            Ws[kq * 4 + 0][row] = wv.x;
            Ws[kq * 4 + 1][row] = wv.y;
            Ws[kq * 4 + 2][row] = wv.z;
            Ws[kq * 4 + 3][row] = wv.w;
        }
        __syncthreads();
#pragma unroll
        for (int k = 0; k < 32; k++) {
            float4 wv = *(const float4*)&Ws[k][ty * 4];
            float4 xv = *(const float4*)&Xs[k][tx * 4];
            float wr[4] = {wv.x, wv.y, wv.z, wv.w};
            float xr[4] = {xv.x, xv.y, xv.z, xv.w};
#pragma unroll
            for (int i = 0; i < 4; i++)
#pragma unroll
                for (int j = 0; j < 4; j++)
                    acc[i][j] = fmaf(wr[i], xr[j], acc[i][j]);
        }
    }

    float* outp = &g_gx[d][t][0][0];
#pragma unroll
    for (int i = 0; i < 4; i++) {
        int g = g0 + ty * 4 + i;
        float bias = b1[g] + b2[g];
        float4 v = {acc[i][0] + bias, acc[i][1] + bias,
                    acc[i][2] + bias, acc[i][3] + bias};
        *(float4*)(outp + (size_t)g * 64 + tx * 4) = v;
    }
}

// ---------------------------------------------------------------------------
// Kernel 2: persistent recurrent kernel. 128 CTAs (64 per direction), 256 thr.
// CTA `cid` owns hidden slice j0 = cid*4 (gate rows j0..j0+3 in each of the
// 3 gate groups). Per step: broadcast-load full h (L2) -> SMEM (transposed
// [k][b]), GEMM 64b x 12rows x 256k against SMEM-resident W_hh slice, gate
// pointwise, write h slice to global double buffer + output, grid barrier.
// ---------------------------------------------------------------------------
__global__ void __launch_bounds__(256, 1) lstm_rec(
    const float* __restrict__ whh_f,
    const float* __restrict__ whh_b,
    float* __restrict__ out)
{
    extern __shared__ float sm[];
    float* w_s    = sm;                 // 12*256
    float* h_s    = sm + 12 * 256;      // 256*64  ([k][b])
    float* gate_s = h_s + 256 * 64;     // 12*64   ([r][b])

    const int dir = (blockIdx.x >= NC) ? 1 : 0;
    const int cid = blockIdx.x - dir * NC;
    const int j0  = cid * HC;
    const float* whh = dir ? whh_b : whh_f;

    const int tid = threadIdx.x;
    const int b   = tid & 63;
    const int rg  = tid >> 6;   // 0..3
    const int jl  = rg;         // local hidden index owned in epilogue
    const int r0  = rg * 3;     // this thread computes local rows r0..r0+2

    // Load W_hh slice (12 rows of 256) into SMEM, coalesced.
    for (int idx = tid; idx < 12 * 256; idx += 256) {
        int r = idx >> 8, k = idx & 255;
        int gr = (r < 4) ? (j0 + r) : (r < 8) ? (256 + j0 + r - 4)
                                              : (512 + j0 + r - 8);
        w_s[idx] = whh[gr * 256 + k];
    }
    // h0 = 0: each CTA zeros its slice of buffer 0.
    g_hbuf[dir][0][(j0 + jl) * 64 + b] = 0.0f;

    // Global gate-row indices for this thread's 3 GEMM rows.
    int gra[3];
#pragma unroll
    for (int q = 0; q < 3; q++) {
        int r = r0 + q;
        gra[q] = (r < 4) ? (j0 + r) : (r < 8) ? (256 + j0 + r - 4)
                                              : (512 + j0 + r - 8);
    }

    float c_reg = 0.0f;

    dir_barrier(dir);  // zeros + weights visible to all CTAs of this dir

    const float* w0 = &w_s[r0 * 256];
    const float* w1 = w0 + 256;
    const float* w2 = w0 + 512;

    for (int s = 0; s < TT; s++) {
        const int t = dir ? (TT - 1 - s) : s;

        // Broadcast-load full h into SMEM ([k][b], conflict-free reads).
        {
            const float4* src = (const float4*)&g_hbuf[dir][s & 1][0];
            float4* dst = (float4*)h_s;
#pragma unroll
            for (int q = 0; q < 16; q++)
                dst[tid + q * 256] = src[tid + q * 256];
        }
        __syncthreads();

        // Accumulators seeded with precomputed input contribution + bias.
        const float* gxt = &g_gx[dir][t][0][0];
        float a0 = gxt[gra[0] * 64 + b];
        float a1 = gxt[gra[1] * 64 + b];
        float a2 = gxt[gra[2] * 64 + b];

        const float* hp = h_s + b;
#pragma unroll 8
        for (int k = 0; k < 256; k += 4) {
            float4 wv0 = *(const float4*)(w0 + k);
            float4 wv1 = *(const float4*)(w1 + k);
            float4 wv2 = *(const float4*)(w2 + k);
            float h0 = hp[(k + 0) * 64];
            float h1 = hp[(k + 1) * 64];
            float h2 = hp[(k + 2) * 64];
            float h3 = hp[(k + 3) * 64];
            a0 = fmaf(wv0.x, h0, a0); a0 = fmaf(wv0.y, h1, a0);
            a0 = fmaf(wv0.z, h2, a0); a0 = fmaf(wv0.w, h3, a0);
            a1 = fmaf(wv1.x, h0, a1); a1 = fmaf(wv1.y, h1, a1);
            a1 = fmaf(wv1.z, h2, a1); a1 = fmaf(wv1.w, h3, a1);
            a2 = fmaf(wv2.x, h0, a2); a2 = fmaf(wv2.y, h1, a2);
            a2 = fmaf(wv2.z, h2, a2); a2 = fmaf(wv2.w, h3, a2);
        }

        gate_s[(r0 + 0) * 64 + b] = a0;
        gate_s[(r0 + 1) * 64 + b] = a1;
        gate_s[(r0 + 2) * 64 + b] = a2;
        __syncthreads();

        // Pointwise gates: thread owns (b, jl). Coupled forget gate = 1 - i.
        float gi = gate_s[jl * 64 + b];
        float gc = gate_s[(4 + jl) * 64 + b];
        float go = gate_s[(8 + jl) * 64 + b];
        float ig = 1.0f / (1.0f + __expf(-gi));
        float cg = tanhf(gc);
        float og = 1.0f / (1.0f + __expf(-go));
        c_reg = (1.0f - ig) * c_reg + ig * cg;
        float h = og * tanhf(c_reg);

        g_hbuf[dir][(s + 1) & 1][(j0 + jl) * 64 + b] = h;
        out[(size_t)t * (BB * 2 * HH) + (size_t)b * (2 * HH)
            + dir * HH + j0 + jl] = h;

        if (s == TT - 1) {
            size_t base = (size_t)TT * BB * 2 * HH;
            out[base + (size_t)b * (2 * HH) + dir * HH + j0 + jl] = h;
            out[base + (size_t)BB * 2 * HH + (size_t)b * (2 * HH)
                + dir * HH + j0 + jl] = c_reg;
        } else {
            dir_barrier(dir);
        }
    }
}

// ---------------------------------------------------------------------------
// Launch. Inputs per metadata order:
// X, wih_f, whh_f, bih_f, bhh_f, wih_b, whh_b, bih_b, bhh_b. Output fp32:
// out[T,B,2H] ++ hn[1,B,2H] ++ cn[1,B,2H].
// ---------------------------------------------------------------------------
extern "C" void kernel_launch(void* const* d_in, const int* in_sizes, int n_in,
                              void* d_out, int out_size) {
    const float* X     = (const float*)d_in[0];
    const float* wih_f = (const float*)d_in[1];
    const float* whh_f = (const float*)d_in[2];
    const float* bih_f = (const float*)d_in[3];
    const float* bhh_f = (const float*)d_in[4];
    const float* wih_b = (const float*)d_in[5];
    const float* whh_b = (const float*)d_in[6];
    const float* bih_b = (const float*)d_in[7];
    const float* bhh_b = (const float*)d_in[8];
    float* out = (float*)d_out;

    const int rec_smem = (12 * 256 + 256 * 64 + 12 * 64) * (int)sizeof(float);
    cudaFuncSetAttribute(lstm_rec, cudaFuncAttributeMaxDynamicSharedMemorySize,
                         rec_smem);

    dim3 gg(TT, G3 / 64, 2);
    gx_gemm<<<gg, 256>>>(X, wih_f, bih_f, bhh_f, wih_b, bih_b, bhh_b);
    lstm_rec<<<2 * NC, 256, rec_smem>>>(whh_f, whh_b, out);
}